// round 3
// baseline (speedup 1.0000x reference)
#include <cuda_runtime.h>

// Problem dims (fixed)
#define B_      8
#define N_      1024
#define IN_DIM  256
#define OUT_DIM 256
#define H_      8
#define D_      32
#define ROWS_   (B_ * N_)          // 8192

// ---------------- static device scratch (no allocations allowed) ----------------
__device__ float           g_inputs[(size_t)ROWS_ * OUT_DIM];   // 32MB: X@W, [row][h*32+d]
__device__ float           g_self[B_ * H_ * N_];                // [b][h][n]
__device__ float           g_neigh[B_ * H_ * N_];               // [b][h][n]
__device__ unsigned short  g_idx[(size_t)ROWS_ * N_];           // 16MB CSR cols (fixed stride)
__device__ int             g_cnt[ROWS_];

// ======================= K1: SGEMM inputs = X @ W =======================
// M=8192, N=256, K=256.  128x128 tile, BK=16, 256 threads, 8x8 microtile.
#define BM 128
#define BN 128
#define BK 16

__global__ __launch_bounds__(256) void k_gemm(const float* __restrict__ X,
                                              const float* __restrict__ W) {
    __shared__ float As[BK][BM];   // transposed A tile
    __shared__ float Bs[BK][BN];

    const int tid  = threadIdx.x;
    const int row0 = blockIdx.y * BM;
    const int col0 = blockIdx.x * BN;
    const int tr   = (tid >> 4) * 8;   // 0..120
    const int tc   = (tid & 15) * 8;   // 0..120

    float acc[8][8];
#pragma unroll
    for (int i = 0; i < 8; i++)
#pragma unroll
        for (int j = 0; j < 8; j++) acc[i][j] = 0.f;

    for (int k0 = 0; k0 < IN_DIM; k0 += BK) {
        // load A tile (BM x BK): 512 float4, 2 per thread, store transposed
#pragma unroll
        for (int l = 0; l < 2; l++) {
            int f  = tid * 2 + l;
            int r  = f >> 2;
            int c4 = (f & 3) * 4;
            float4 v = *(const float4*)(X + (size_t)(row0 + r) * IN_DIM + k0 + c4);
            As[c4 + 0][r] = v.x;
            As[c4 + 1][r] = v.y;
            As[c4 + 2][r] = v.z;
            As[c4 + 3][r] = v.w;
        }
        // load B tile (BK x BN): 512 float4, 2 per thread
#pragma unroll
        for (int l = 0; l < 2; l++) {
            int f  = tid * 2 + l;
            int r  = f >> 5;
            int c4 = (f & 31) * 4;
            float4 v = *(const float4*)(W + (size_t)(k0 + r) * OUT_DIM + col0 + c4);
            *(float4*)&Bs[r][c4] = v;
        }
        __syncthreads();

#pragma unroll
        for (int k = 0; k < BK; k++) {
            float a[8], b[8];
            *(float4*)&a[0] = *(const float4*)&As[k][tr];
            *(float4*)&a[4] = *(const float4*)&As[k][tr + 4];
            *(float4*)&b[0] = *(const float4*)&Bs[k][tc];
            *(float4*)&b[4] = *(const float4*)&Bs[k][tc + 4];
#pragma unroll
            for (int i = 0; i < 8; i++)
#pragma unroll
                for (int j = 0; j < 8; j++) acc[i][j] = fmaf(a[i], b[j], acc[i][j]);
        }
        __syncthreads();
    }

#pragma unroll
    for (int i = 0; i < 8; i++) {
        float* dst = g_inputs + (size_t)(row0 + tr + i) * OUT_DIM + col0 + tc;
        float4 v0 = {acc[i][0], acc[i][1], acc[i][2], acc[i][3]};
        float4 v1 = {acc[i][4], acc[i][5], acc[i][6], acc[i][7]};
        *(float4*)(dst)     = v0;
        *(float4*)(dst + 4) = v1;
    }
}

// ======================= K2: self/neigh attention scores =======================
// thread handles one (row, h): s1 = <inputs[row,h,:], fc1[h]>, s2 likewise fc2.
__global__ __launch_bounds__(256) void k_scores(const float* __restrict__ fc1,
                                                const float* __restrict__ fc2) {
    __shared__ float f1[H_ * D_];
    __shared__ float f2[H_ * D_];
    int t = threadIdx.x;
    f1[t] = fc1[t];
    f2[t] = fc2[t];
    __syncthreads();

    int gid = blockIdx.x * 256 + t;
    int row = gid >> 3;
    int h   = gid & 7;
    const float* ip = g_inputs + (size_t)row * OUT_DIM + h * D_;

    float s1 = 0.f, s2 = 0.f;
#pragma unroll
    for (int i = 0; i < D_; i += 4) {
        float4 v = *(const float4*)(ip + i);
        float4 a = *(const float4*)(f1 + h * D_ + i);
        float4 b = *(const float4*)(f2 + h * D_ + i);
        s1 += v.x * a.x + v.y * a.y + v.z * a.z + v.w * a.w;
        s2 += v.x * b.x + v.y * b.y + v.z * b.z + v.w * b.w;
    }
    int b_ = row >> 10;
    int n  = row & (N_ - 1);
    g_self [(b_ * H_ + h) * N_ + n] = s1;
    g_neigh[(b_ * H_ + h) * N_ + n] = s2;
}

// ======================= K3: adjacency -> CSR (ballot compaction) =======================
// warp per row; A entries are exactly 0.0 or 1.0.
__global__ __launch_bounds__(256) void k_csr(const float* __restrict__ A) {
    int warp = threadIdx.x >> 5;
    int lane = threadIdx.x & 31;
    int row  = blockIdx.x * 8 + warp;

    const float* Arow = A + (size_t)row * N_;
    unsigned short* out = g_idx + (size_t)row * N_;

    int base = 0;
#pragma unroll
    for (int it = 0; it < 8; it++) {
        float4 v = *(const float4*)(Arow + it * 128 + lane * 4);
        float vals[4] = {v.x, v.y, v.z, v.w};
#pragma unroll
        for (int e = 0; e < 4; e++) {
            bool nz = (vals[e] != 0.f);
            unsigned mask = __ballot_sync(0xffffffffu, nz);
            if (nz) {
                int pos = base + __popc(mask & ((1u << lane) - 1u));
                out[pos] = (unsigned short)(it * 128 + lane * 4 + e);
            }
            base += __popc(mask);
        }
    }
    if (lane == 0) g_cnt[row] = base;
}

// ======================= K4: sparse softmax-attention aggregation =======================
// CTA per (b, h, row-block of 512). V_h for the whole batch-head lives in smem (128KB).
// Lane layout: g = lane>>3 selects 1 of 4 simultaneous neighbors, s = lane&7 -> dims [4s,4s+4).
// LDS.128 phases (8 lanes each) are per-group -> conflict-free at the 128B/cyc floor.
__global__ __launch_bounds__(512) void k_attn(float* __restrict__ out) {
    extern __shared__ float sm[];
    float* Vs = sm;                 // [1024][32]
    float* ns = sm + N_ * D_;       // [1024]

    const int b  = blockIdx.z;
    const int h  = blockIdx.y;
    const int rb = blockIdx.x;
    const int tid = threadIdx.x;

    // stage V_h = inputs[b, :, h, :]
    const float* src = g_inputs + ((size_t)b * N_) * OUT_DIM + h * D_;
    for (int f = tid; f < N_ * D_ / 4; f += 512) {
        int m  = f >> 3;
        int d4 = (f & 7) << 2;
        *(float4*)&Vs[m * D_ + d4] = *(const float4*)(src + (size_t)m * OUT_DIM + d4);
    }
    const float* nsrc = g_neigh + (b * H_ + h) * N_;
    for (int m = tid; m < N_; m += 512) ns[m] = nsrc[m];
    __syncthreads();

    const int warp = tid >> 5;
    const int lane = tid & 31;
    const int g    = lane >> 3;
    const int s    = lane & 7;
    const int rbase = rb * 512;

    for (int n = rbase + warp; n < rbase + 512; n += 16) {
        const int row = b * N_ + n;
        const int nb  = g_cnt[row];
        const float self = g_self[(b * H_ + h) * N_ + n];
        const unsigned short* ip = g_idx + (size_t)row * N_;

        float4 acc = {0.f, 0.f, 0.f, 0.f};
        float psum = 0.f;

        for (int base = 0; base < nb; base += 32) {
            int cn = nb - base;
            if (cn > 32) cn = 32;
            unsigned m = 0;
            float p = 0.f;
            if (lane < cn) {
                m = ip[base + lane];
                float sc = self + ns[m];
                sc = (sc >= 0.f) ? sc : 0.01f * sc;   // leaky_relu(0.01)
                p = __expf(sc);                        // bounded scores: no max-sub needed
            }
            psum += p;
            for (int j4 = 0; j4 < cn; j4 += 4) {
                float    pj = __shfl_sync(0xffffffffu, p, j4 + g);
                unsigned mj = __shfl_sync(0xffffffffu, m, j4 + g);
                float4 v = *(const float4*)&Vs[mj * D_ + 4 * s];
                acc.x = fmaf(pj, v.x, acc.x);
                acc.y = fmaf(pj, v.y, acc.y);
                acc.z = fmaf(pj, v.z, acc.z);
                acc.w = fmaf(pj, v.w, acc.w);
            }
        }

        // reduce denominator over all 32 lanes
#pragma unroll
        for (int off = 16; off; off >>= 1) psum += __shfl_xor_sync(0xffffffffu, psum, off);
        // reduce acc across the 4 neighbor-groups (lane bits 3..4)
        acc.x += __shfl_xor_sync(0xffffffffu, acc.x, 8);
        acc.y += __shfl_xor_sync(0xffffffffu, acc.y, 8);
        acc.z += __shfl_xor_sync(0xffffffffu, acc.z, 8);
        acc.w += __shfl_xor_sync(0xffffffffu, acc.w, 8);
        acc.x += __shfl_xor_sync(0xffffffffu, acc.x, 16);
        acc.y += __shfl_xor_sync(0xffffffffu, acc.y, 16);
        acc.z += __shfl_xor_sync(0xffffffffu, acc.z, 16);
        acc.w += __shfl_xor_sync(0xffffffffu, acc.w, 16);

        const float inv = 1.f / psum;
        if (g == 0) {
            float4 o;
            o.x = fmaxf(acc.x * inv, 0.f);
            o.y = fmaxf(acc.y * inv, 0.f);
            o.z = fmaxf(acc.z * inv, 0.f);
            o.w = fmaxf(acc.w * inv, 0.f);
            *(float4*)(out + ((size_t)(b * N_ + n)) * OUT_DIM + h * D_ + 4 * s) = o;
        }
    }
}

// ======================= launch =======================
extern "C" void kernel_launch(void* const* d_in, const int* in_sizes, int n_in,
                              void* d_out, int out_size) {
    const float* A   = (const float*)d_in[0];
    const float* X   = (const float*)d_in[1];
    const float* W   = (const float*)d_in[2];
    const float* fc1 = (const float*)d_in[3];
    const float* fc2 = (const float*)d_in[4];
    float* out = (float*)d_out;

    const size_t smem4 = (size_t)(N_ * D_ + N_) * sizeof(float);   // 135168 B
    cudaFuncSetAttribute(k_attn, cudaFuncAttributeMaxDynamicSharedMemorySize, (int)smem4);

    dim3 g1(OUT_DIM / BN, ROWS_ / BM);   // (2, 64)
    k_gemm<<<g1, 256>>>(X, W);
    k_scores<<<(ROWS_ * H_) / 256, 256>>>(fc1, fc2);
    k_csr<<<ROWS_ / 8, 256>>>(A);
    k_attn<<<dim3(2, H_, B_), 512, smem4>>>(out);
}

// round 4
// speedup vs baseline: 1.0918x; 1.0918x over previous
#include <cuda_runtime.h>

// Problem dims (fixed)
#define B_      8
#define N_      1024
#define IN_DIM  256
#define OUT_DIM 256
#define H_      8
#define D_      32
#define ROWS_   (B_ * N_)          // 8192

// ---------------- static device scratch (no allocations allowed) ----------------
__device__ float           g_inputs[(size_t)ROWS_ * OUT_DIM];   // 32MB: X@W, [row][h*32+d]
__device__ float           g_self[B_ * H_ * N_];                // [b][h][n]
__device__ float           g_neigh[B_ * H_ * N_];               // [b][h][n]
__device__ unsigned short  g_idx[(size_t)ROWS_ * N_];           // 16MB CSR cols (fixed stride)
__device__ int             g_cnt[ROWS_];

// ======================= K1: SGEMM inputs = X @ W =======================
// M=8192, N=256, K=256.  128x128 tile, BK=16, 256 threads, 8x8 microtile.
#define BM 128
#define BN 128
#define BK 16

__global__ __launch_bounds__(256) void k_gemm(const float* __restrict__ X,
                                              const float* __restrict__ W) {
    __shared__ float As[BK][BM];   // transposed A tile
    __shared__ float Bs[BK][BN];

    const int tid  = threadIdx.x;
    const int row0 = blockIdx.y * BM;
    const int col0 = blockIdx.x * BN;
    const int tr   = (tid >> 4) * 8;   // 0..120
    const int tc   = (tid & 15) * 8;   // 0..120

    float acc[8][8];
#pragma unroll
    for (int i = 0; i < 8; i++)
#pragma unroll
        for (int j = 0; j < 8; j++) acc[i][j] = 0.f;

    for (int k0 = 0; k0 < IN_DIM; k0 += BK) {
#pragma unroll
        for (int l = 0; l < 2; l++) {
            int f  = tid * 2 + l;
            int r  = f >> 2;
            int c4 = (f & 3) * 4;
            float4 v = *(const float4*)(X + (size_t)(row0 + r) * IN_DIM + k0 + c4);
            As[c4 + 0][r] = v.x;
            As[c4 + 1][r] = v.y;
            As[c4 + 2][r] = v.z;
            As[c4 + 3][r] = v.w;
        }
#pragma unroll
        for (int l = 0; l < 2; l++) {
            int f  = tid * 2 + l;
            int r  = f >> 5;
            int c4 = (f & 31) * 4;
            float4 v = *(const float4*)(W + (size_t)(k0 + r) * OUT_DIM + col0 + c4);
            *(float4*)&Bs[r][c4] = v;
        }
        __syncthreads();

#pragma unroll
        for (int k = 0; k < BK; k++) {
            float a[8], b[8];
            *(float4*)&a[0] = *(const float4*)&As[k][tr];
            *(float4*)&a[4] = *(const float4*)&As[k][tr + 4];
            *(float4*)&b[0] = *(const float4*)&Bs[k][tc];
            *(float4*)&b[4] = *(const float4*)&Bs[k][tc + 4];
#pragma unroll
            for (int i = 0; i < 8; i++)
#pragma unroll
                for (int j = 0; j < 8; j++) acc[i][j] = fmaf(a[i], b[j], acc[i][j]);
        }
        __syncthreads();
    }

#pragma unroll
    for (int i = 0; i < 8; i++) {
        float* dst = g_inputs + (size_t)(row0 + tr + i) * OUT_DIM + col0 + tc;
        float4 v0 = {acc[i][0], acc[i][1], acc[i][2], acc[i][3]};
        float4 v1 = {acc[i][4], acc[i][5], acc[i][6], acc[i][7]};
        *(float4*)(dst)     = v0;
        *(float4*)(dst + 4) = v1;
    }
}

// ======================= K2: self/neigh attention scores =======================
__global__ __launch_bounds__(256) void k_scores(const float* __restrict__ fc1,
                                                const float* __restrict__ fc2) {
    __shared__ float f1[H_ * D_];
    __shared__ float f2[H_ * D_];
    int t = threadIdx.x;
    f1[t] = fc1[t];
    f2[t] = fc2[t];
    __syncthreads();

    int gid = blockIdx.x * 256 + t;
    int row = gid >> 3;
    int h   = gid & 7;
    const float* ip = g_inputs + (size_t)row * OUT_DIM + h * D_;

    float s1 = 0.f, s2 = 0.f;
#pragma unroll
    for (int i = 0; i < D_; i += 4) {
        float4 v = *(const float4*)(ip + i);
        float4 a = *(const float4*)(f1 + h * D_ + i);
        float4 b = *(const float4*)(f2 + h * D_ + i);
        s1 += v.x * a.x + v.y * a.y + v.z * a.z + v.w * a.w;
        s2 += v.x * b.x + v.y * b.y + v.z * b.z + v.w * b.w;
    }
    int b_ = row >> 10;
    int n  = row & (N_ - 1);
    g_self [(b_ * H_ + h) * N_ + n] = s1;
    g_neigh[(b_ * H_ + h) * N_ + n] = s2;
}

// ======================= K3: adjacency -> CSR (ballot compaction) =======================
__global__ __launch_bounds__(256) void k_csr(const float* __restrict__ A) {
    int warp = threadIdx.x >> 5;
    int lane = threadIdx.x & 31;
    int row  = blockIdx.x * 8 + warp;

    const float* Arow = A + (size_t)row * N_;
    unsigned short* out = g_idx + (size_t)row * N_;

    int base = 0;
#pragma unroll
    for (int it = 0; it < 8; it++) {
        float4 v = *(const float4*)(Arow + it * 128 + lane * 4);
        float vals[4] = {v.x, v.y, v.z, v.w};
#pragma unroll
        for (int e = 0; e < 4; e++) {
            bool nz = (vals[e] != 0.f);
            unsigned mask = __ballot_sync(0xffffffffu, nz);
            if (nz) {
                int pos = base + __popc(mask & ((1u << lane) - 1u));
                out[pos] = (unsigned short)(it * 128 + lane * 4 + e);
            }
            base += __popc(mask);
        }
    }
    if (lane == 0) g_cnt[row] = base;
}

// ======================= K4: sparse softmax-attention aggregation =======================
// CTA per (b, h, row-block of 512). V_h (128KB) + neigh scores (4KB) in smem.
// Lane layout: g = lane>>3 picks 1-of-4 simultaneous edges, s = lane&7 -> dims [4s,4s+4).
// First 64 neighbor slots are register-resident (m0/p0, m1/p1) so the 16 FFMA
// steps fully unroll into independent SHFL/LDS chains; rows with nb>64 (~3%)
// take a dynamic tail loop.
__global__ __launch_bounds__(512) void k_attn(float* __restrict__ out) {
    extern __shared__ float sm[];
    float* Vs = sm;                 // [1024][32]
    float* ns = sm + N_ * D_;       // [1024]

    const int b  = blockIdx.z;
    const int h  = blockIdx.y;
    const int rb = blockIdx.x;
    const int tid = threadIdx.x;

    // stage V_h = inputs[b, :, h, :]
    const float* src = g_inputs + ((size_t)b * N_) * OUT_DIM + h * D_;
    for (int f = tid; f < N_ * D_ / 4; f += 512) {
        int m  = f >> 3;
        int d4 = (f & 7) << 2;
        *(float4*)&Vs[m * D_ + d4] = *(const float4*)(src + (size_t)m * OUT_DIM + d4);
    }
    const float* nsrc = g_neigh + (b * H_ + h) * N_;
    for (int m = tid; m < N_; m += 512) ns[m] = nsrc[m];
    __syncthreads();

    const int warp = tid >> 5;
    const int lane = tid & 31;
    const int g    = lane >> 3;
    const int s    = lane & 7;
    const int rbase = rb * 512;

    for (int n = rbase + warp; n < rbase + 512; n += 16) {
        const int row = b * N_ + n;
        const int nb  = g_cnt[row];
        const float self = g_self[(b * H_ + h) * N_ + n];
        const unsigned short* ip = g_idx + (size_t)row * N_;

        // ---- front: load up to 64 neighbor slots into registers, all long-lat ops overlap
        unsigned m0 = 0, m1 = 0;
        float p0 = 0.f, p1 = 0.f;
        const bool a0 = (lane < nb);
        const bool a1 = (lane + 32 < nb);
        if (a0) m0 = ip[lane];
        if (a1) m1 = ip[lane + 32];
        if (a0) {
            float sc = self + ns[m0];
            sc = (sc >= 0.f) ? sc : 0.01f * sc;
            p0 = __expf(sc);
        }
        if (a1) {
            float sc = self + ns[m1];
            sc = (sc >= 0.f) ? sc : 0.01f * sc;
            p1 = __expf(sc);
        }
        float psum = p0 + p1;
        float4 acc = {0.f, 0.f, 0.f, 0.f};

        // ---- rare tail: nb > 64 (dynamic loop, unrolled fixed body)
        for (int base = 64; base < nb; base += 32) {
            unsigned m = 0;
            float p = 0.f;
            if (base + lane < nb) {
                m = ip[base + lane];
                float sc = self + ns[m];
                sc = (sc >= 0.f) ? sc : 0.01f * sc;
                p = __expf(sc);
            }
            psum += p;
#pragma unroll
            for (int t = 0; t < 8; t++) {
                float    pj = __shfl_sync(0xffffffffu, p, 4 * t + g);
                unsigned mj = __shfl_sync(0xffffffffu, m, 4 * t + g);
                float4 v = *(const float4*)&Vs[mj * D_ + 4 * s];
                acc.x = fmaf(pj, v.x, acc.x);
                acc.y = fmaf(pj, v.y, acc.y);
                acc.z = fmaf(pj, v.z, acc.z);
                acc.w = fmaf(pj, v.w, acc.w);
            }
        }

        // ---- main body: 16 fully-unrolled independent steps over the 64 register slots
#pragma unroll
        for (int t = 0; t < 8; t++) {
            float    pj = __shfl_sync(0xffffffffu, p0, 4 * t + g);
            unsigned mj = __shfl_sync(0xffffffffu, m0, 4 * t + g);
            float4 v = *(const float4*)&Vs[mj * D_ + 4 * s];
            acc.x = fmaf(pj, v.x, acc.x);
            acc.y = fmaf(pj, v.y, acc.y);
            acc.z = fmaf(pj, v.z, acc.z);
            acc.w = fmaf(pj, v.w, acc.w);
        }
#pragma unroll
        for (int t = 0; t < 8; t++) {
            float    pj = __shfl_sync(0xffffffffu, p1, 4 * t + g);
            unsigned mj = __shfl_sync(0xffffffffu, m1, 4 * t + g);
            float4 v = *(const float4*)&Vs[mj * D_ + 4 * s];
            acc.x = fmaf(pj, v.x, acc.x);
            acc.y = fmaf(pj, v.y, acc.y);
            acc.z = fmaf(pj, v.z, acc.z);
            acc.w = fmaf(pj, v.w, acc.w);
        }

        // reduce denominator over all 32 lanes
#pragma unroll
        for (int off = 16; off; off >>= 1) psum += __shfl_xor_sync(0xffffffffu, psum, off);
        // reduce acc across the 4 edge-groups (lane bits 3..4)
        acc.x += __shfl_xor_sync(0xffffffffu, acc.x, 8);
        acc.y += __shfl_xor_sync(0xffffffffu, acc.y, 8);
        acc.z += __shfl_xor_sync(0xffffffffu, acc.z, 8);
        acc.w += __shfl_xor_sync(0xffffffffu, acc.w, 8);
        acc.x += __shfl_xor_sync(0xffffffffu, acc.x, 16);
        acc.y += __shfl_xor_sync(0xffffffffu, acc.y, 16);
        acc.z += __shfl_xor_sync(0xffffffffu, acc.z, 16);
        acc.w += __shfl_xor_sync(0xffffffffu, acc.w, 16);

        const float inv = 1.f / psum;
        if (g == 0) {
            float4 o;
            o.x = fmaxf(acc.x * inv, 0.f);
            o.y = fmaxf(acc.y * inv, 0.f);
            o.z = fmaxf(acc.z * inv, 0.f);
            o.w = fmaxf(acc.w * inv, 0.f);
            *(float4*)(out + ((size_t)(b * N_ + n)) * OUT_DIM + h * D_ + 4 * s) = o;
        }
    }
}

// ======================= launch =======================
extern "C" void kernel_launch(void* const* d_in, const int* in_sizes, int n_in,
                              void* d_out, int out_size) {
    const float* A   = (const float*)d_in[0];
    const float* X   = (const float*)d_in[1];
    const float* W   = (const float*)d_in[2];
    const float* fc1 = (const float*)d_in[3];
    const float* fc2 = (const float*)d_in[4];
    float* out = (float*)d_out;

    const size_t smem4 = (size_t)(N_ * D_ + N_) * sizeof(float);   // 135168 B
    cudaFuncSetAttribute(k_attn, cudaFuncAttributeMaxDynamicSharedMemorySize, (int)smem4);

    dim3 g1(OUT_DIM / BN, ROWS_ / BM);   // (2, 64)
    k_gemm<<<g1, 256>>>(X, W);
    k_scores<<<(ROWS_ * H_) / 256, 256>>>(fc1, fc2);
    k_csr<<<ROWS_ / 8, 256>>>(A);
    k_attn<<<dim3(2, H_, B_), 512, smem4>>>(out);
}

// round 5
// speedup vs baseline: 1.2277x; 1.1244x over previous
#include <cuda_runtime.h>
#include <cuda_fp16.h>

// Problem dims (fixed)
#define B_      8
#define N_      1024
#define IN_DIM  256
#define OUT_DIM 256
#define H_      8
#define D_      32
#define ROWS_   (B_ * N_)          // 8192

// ---------------- static device scratch (no allocations allowed) ----------------
__device__ float           g_inputs[(size_t)ROWS_ * OUT_DIM];   // 32MB: X@W, [row][h*32+d]
__device__ float           g_self[B_ * H_ * N_];                // [b][h][n]
__device__ float           g_neigh[B_ * H_ * N_];               // [b][h][n]
__device__ unsigned short  g_idx[(size_t)ROWS_ * N_];           // 16MB CSR cols (fixed stride)
__device__ int             g_cnt[ROWS_];

// ======================= K1: SGEMM inputs = X @ W =======================
// M=8192, N=256, K=256.  128x128 tile, BK=16, 256 threads, 8x8 microtile.
#define BM 128
#define BN 128
#define BK 16

__global__ __launch_bounds__(256) void k_gemm(const float* __restrict__ X,
                                              const float* __restrict__ W) {
    __shared__ float As[BK][BM];   // transposed A tile
    __shared__ float Bs[BK][BN];

    const int tid  = threadIdx.x;
    const int row0 = blockIdx.y * BM;
    const int col0 = blockIdx.x * BN;
    const int tr   = (tid >> 4) * 8;   // 0..120
    const int tc   = (tid & 15) * 8;   // 0..120

    float acc[8][8];
#pragma unroll
    for (int i = 0; i < 8; i++)
#pragma unroll
        for (int j = 0; j < 8; j++) acc[i][j] = 0.f;

    for (int k0 = 0; k0 < IN_DIM; k0 += BK) {
#pragma unroll
        for (int l = 0; l < 2; l++) {
            int f  = tid * 2 + l;
            int r  = f >> 2;
            int c4 = (f & 3) * 4;
            float4 v = *(const float4*)(X + (size_t)(row0 + r) * IN_DIM + k0 + c4);
            As[c4 + 0][r] = v.x;
            As[c4 + 1][r] = v.y;
            As[c4 + 2][r] = v.z;
            As[c4 + 3][r] = v.w;
        }
#pragma unroll
        for (int l = 0; l < 2; l++) {
            int f  = tid * 2 + l;
            int r  = f >> 5;
            int c4 = (f & 31) * 4;
            float4 v = *(const float4*)(W + (size_t)(k0 + r) * OUT_DIM + col0 + c4);
            *(float4*)&Bs[r][c4] = v;
        }
        __syncthreads();

#pragma unroll
        for (int k = 0; k < BK; k++) {
            float a[8], b[8];
            *(float4*)&a[0] = *(const float4*)&As[k][tr];
            *(float4*)&a[4] = *(const float4*)&As[k][tr + 4];
            *(float4*)&b[0] = *(const float4*)&Bs[k][tc];
            *(float4*)&b[4] = *(const float4*)&Bs[k][tc + 4];
#pragma unroll
            for (int i = 0; i < 8; i++)
#pragma unroll
                for (int j = 0; j < 8; j++) acc[i][j] = fmaf(a[i], b[j], acc[i][j]);
        }
        __syncthreads();
    }

#pragma unroll
    for (int i = 0; i < 8; i++) {
        float* dst = g_inputs + (size_t)(row0 + tr + i) * OUT_DIM + col0 + tc;
        float4 v0 = {acc[i][0], acc[i][1], acc[i][2], acc[i][3]};
        float4 v1 = {acc[i][4], acc[i][5], acc[i][6], acc[i][7]};
        *(float4*)(dst)     = v0;
        *(float4*)(dst + 4) = v1;
    }
}

// ======================= K2: self/neigh attention scores =======================
__global__ __launch_bounds__(256) void k_scores(const float* __restrict__ fc1,
                                                const float* __restrict__ fc2) {
    __shared__ float f1[H_ * D_];
    __shared__ float f2[H_ * D_];
    int t = threadIdx.x;
    f1[t] = fc1[t];
    f2[t] = fc2[t];
    __syncthreads();

    int gid = blockIdx.x * 256 + t;
    int row = gid >> 3;
    int h   = gid & 7;
    const float* ip = g_inputs + (size_t)row * OUT_DIM + h * D_;

    float s1 = 0.f, s2 = 0.f;
#pragma unroll
    for (int i = 0; i < D_; i += 4) {
        float4 v = *(const float4*)(ip + i);
        float4 a = *(const float4*)(f1 + h * D_ + i);
        float4 b = *(const float4*)(f2 + h * D_ + i);
        s1 += v.x * a.x + v.y * a.y + v.z * a.z + v.w * a.w;
        s2 += v.x * b.x + v.y * b.y + v.z * b.z + v.w * b.w;
    }
    int b_ = row >> 10;
    int n  = row & (N_ - 1);
    g_self [(b_ * H_ + h) * N_ + n] = s1;
    g_neigh[(b_ * H_ + h) * N_ + n] = s2;
}

// ======================= K3: adjacency -> CSR (ballot compaction) =======================
__global__ __launch_bounds__(256) void k_csr(const float* __restrict__ A) {
    int warp = threadIdx.x >> 5;
    int lane = threadIdx.x & 31;
    int row  = blockIdx.x * 8 + warp;

    const float* Arow = A + (size_t)row * N_;
    unsigned short* out = g_idx + (size_t)row * N_;

    int base = 0;
#pragma unroll
    for (int it = 0; it < 8; it++) {
        float4 v = *(const float4*)(Arow + it * 128 + lane * 4);
        float vals[4] = {v.x, v.y, v.z, v.w};
#pragma unroll
        for (int e = 0; e < 4; e++) {
            bool nz = (vals[e] != 0.f);
            unsigned mask = __ballot_sync(0xffffffffu, nz);
            if (nz) {
                int pos = base + __popc(mask & ((1u << lane) - 1u));
                out[pos] = (unsigned short)(it * 128 + lane * 4 + e);
            }
            base += __popc(mask);
        }
    }
    if (lane == 0) g_cnt[row] = base;
}

// ======================= K4: sparse softmax-attention aggregation =======================
// fp16 V tile (64KB) + fp32 neigh scores (4KB) = 68KB smem -> 2 CTAs/SM, 32 warps.
// Lane layout: g = lane>>3 picks 1-of-4 edges per step, s = lane&7 -> dims [4s,4s+4).
// (p, m) travel in ONE shfl word: m (10 bits) packed into p's low mantissa bits
// (<=2.4e-4 relative perturbation of the weight; denominator uses exact p).
#define RB 8   // row-blocks per (b,h) -> 128 rows per CTA, grid = 512 CTAs

__global__ __launch_bounds__(512, 2) void k_attn(float* __restrict__ out) {
    extern __shared__ char smraw[];
    __half* Vs = (__half*)smraw;                       // [1024][32] fp16
    float*  ns = (float*)(smraw + N_ * D_ * 2);        // [1024]

    const int b  = blockIdx.z;
    const int h  = blockIdx.y;
    const int rb = blockIdx.x;
    const int tid = threadIdx.x;

    // stage V_h = fp16(inputs[b, :, h, :])
    const float* src = g_inputs + ((size_t)b * N_) * OUT_DIM + h * D_;
    for (int f = tid; f < N_ * D_ / 4; f += 512) {
        int m  = f >> 3;
        int d4 = (f & 7) << 2;
        float4 v = *(const float4*)(src + (size_t)m * OUT_DIM + d4);
        __half2 h01 = __floats2half2_rn(v.x, v.y);
        __half2 h23 = __floats2half2_rn(v.z, v.w);
        uint2 pk;
        pk.x = *(unsigned*)&h01;
        pk.y = *(unsigned*)&h23;
        *(uint2*)(Vs + m * D_ + d4) = pk;
    }
    const float* nsrc = g_neigh + (b * H_ + h) * N_;
    for (int m = tid; m < N_; m += 512) ns[m] = nsrc[m];
    __syncthreads();

    const int warp = tid >> 5;
    const int lane = tid & 31;
    const int g    = lane >> 3;
    const int s    = lane & 7;
    const int rbase = rb * (N_ / RB);

    for (int n = rbase + warp; n < rbase + N_ / RB; n += 16) {
        const int row = b * N_ + n;
        const int nb  = g_cnt[row];
        const float self = g_self[(b * H_ + h) * N_ + n];
        const unsigned short* ip = g_idx + (size_t)row * N_;

        // ---- front: 64 slots -> exact p for denominator, packed (p|m) for the body
        unsigned m0 = 0, m1 = 0;
        float p0 = 0.f, p1 = 0.f;
        const bool a0 = (lane < nb);
        const bool a1 = (lane + 32 < nb);
        if (a0) m0 = ip[lane];
        if (a1) m1 = ip[lane + 32];
        if (a0) {
            float sc = self + ns[m0];
            sc = (sc >= 0.f) ? sc : 0.01f * sc;
            p0 = __expf(sc);
        }
        if (a1) {
            float sc = self + ns[m1];
            sc = (sc >= 0.f) ? sc : 0.01f * sc;
            p1 = __expf(sc);
        }
        float psum = p0 + p1;
        const unsigned pm0 = (__float_as_uint(p0) & ~1023u) | m0;  // inactive: 0|0 = 0
        const unsigned pm1 = (__float_as_uint(p1) & ~1023u) | m1;
        float4 acc = {0.f, 0.f, 0.f, 0.f};

        // ---- rare tail: nb > 64
        for (int base = 64; base < nb; base += 32) {
            unsigned mt = 0;
            float pt = 0.f;
            if (base + lane < nb) {
                mt = ip[base + lane];
                float sc = self + ns[mt];
                sc = (sc >= 0.f) ? sc : 0.01f * sc;
                pt = __expf(sc);
            }
            psum += pt;
            unsigned pmt = (__float_as_uint(pt) & ~1023u) | mt;
#pragma unroll
            for (int t = 0; t < 8; t++) {
                unsigned pmj = __shfl_sync(0xffffffffu, pmt, 4 * t + g);
                float    pj  = __uint_as_float(pmj);     // m bits = tiny mantissa noise
                unsigned mj  = pmj & 1023u;
                uint2 hv = *(const uint2*)(Vs + (mj << 5) + (s << 2));
                float2 f01 = __half22float2(*(__half2*)&hv.x);
                float2 f23 = __half22float2(*(__half2*)&hv.y);
                acc.x = fmaf(pj, f01.x, acc.x);
                acc.y = fmaf(pj, f01.y, acc.y);
                acc.z = fmaf(pj, f23.x, acc.z);
                acc.w = fmaf(pj, f23.y, acc.w);
            }
        }

        // ---- main body: 16 fully-unrolled independent steps, one shfl each
#pragma unroll
        for (int t = 0; t < 8; t++) {
            unsigned pmj = __shfl_sync(0xffffffffu, pm0, 4 * t + g);
            float    pj  = __uint_as_float(pmj);
            unsigned mj  = pmj & 1023u;
            uint2 hv = *(const uint2*)(Vs + (mj << 5) + (s << 2));
            float2 f01 = __half22float2(*(__half2*)&hv.x);
            float2 f23 = __half22float2(*(__half2*)&hv.y);
            acc.x = fmaf(pj, f01.x, acc.x);
            acc.y = fmaf(pj, f01.y, acc.y);
            acc.z = fmaf(pj, f23.x, acc.z);
            acc.w = fmaf(pj, f23.y, acc.w);
        }
#pragma unroll
        for (int t = 0; t < 8; t++) {
            unsigned pmj = __shfl_sync(0xffffffffu, pm1, 4 * t + g);
            float    pj  = __uint_as_float(pmj);
            unsigned mj  = pmj & 1023u;
            uint2 hv = *(const uint2*)(Vs + (mj << 5) + (s << 2));
            float2 f01 = __half22float2(*(__half2*)&hv.x);
            float2 f23 = __half22float2(*(__half2*)&hv.y);
            acc.x = fmaf(pj, f01.x, acc.x);
            acc.y = fmaf(pj, f01.y, acc.y);
            acc.z = fmaf(pj, f23.x, acc.z);
            acc.w = fmaf(pj, f23.y, acc.w);
        }

        // reduce denominator over all 32 lanes
#pragma unroll
        for (int off = 16; off; off >>= 1) psum += __shfl_xor_sync(0xffffffffu, psum, off);
        // reduce acc across the 4 edge-groups (lane bits 3..4)
        acc.x += __shfl_xor_sync(0xffffffffu, acc.x, 8);
        acc.y += __shfl_xor_sync(0xffffffffu, acc.y, 8);
        acc.z += __shfl_xor_sync(0xffffffffu, acc.z, 8);
        acc.w += __shfl_xor_sync(0xffffffffu, acc.w, 8);
        acc.x += __shfl_xor_sync(0xffffffffu, acc.x, 16);
        acc.y += __shfl_xor_sync(0xffffffffu, acc.y, 16);
        acc.z += __shfl_xor_sync(0xffffffffu, acc.z, 16);
        acc.w += __shfl_xor_sync(0xffffffffu, acc.w, 16);

        const float inv = 1.f / psum;
        if (g == 0) {
            float4 o;
            o.x = fmaxf(acc.x * inv, 0.f);
            o.y = fmaxf(acc.y * inv, 0.f);
            o.z = fmaxf(acc.z * inv, 0.f);
            o.w = fmaxf(acc.w * inv, 0.f);
            *(float4*)(out + ((size_t)(b * N_ + n)) * OUT_DIM + h * D_ + 4 * s) = o;
        }
    }
}

// ======================= launch =======================
extern "C" void kernel_launch(void* const* d_in, const int* in_sizes, int n_in,
                              void* d_out, int out_size) {
    const float* A   = (const float*)d_in[0];
    const float* X   = (const float*)d_in[1];
    const float* W   = (const float*)d_in[2];
    const float* fc1 = (const float*)d_in[3];
    const float* fc2 = (const float*)d_in[4];
    float* out = (float*)d_out;

    const size_t smem4 = (size_t)N_ * D_ * 2 + (size_t)N_ * sizeof(float);   // 69632 B
    cudaFuncSetAttribute(k_attn, cudaFuncAttributeMaxDynamicSharedMemorySize, (int)smem4);

    dim3 g1(OUT_DIM / BN, ROWS_ / BM);   // (2, 64)
    k_gemm<<<g1, 256>>>(X, W);
    k_scores<<<(ROWS_ * H_) / 256, 256>>>(fc1, fc2);
    k_csr<<<ROWS_ / 8, 256>>>(A);
    k_attn<<<dim3(RB, H_, B_), 512, smem4>>>(out);
}